// round 1
// baseline (speedup 1.0000x reference)
#include <cuda_runtime.h>

// LateralInhibition: out = X * ((X @ W_diag0 + b) > 0)
// X: (M=32768, 512) fp32 row-major, W: (512,512) fp32 row-major (K-major),
// b: (512,) fp32. Fused SIMT fp32 GEMM + gate epilogue.

#define NDIM 512
#define BM 128
#define BN 128
#define BK 16
#define TM 8
#define TN 8
#define NTHREADS 256

__global__ __launch_bounds__(NTHREADS, 2)
void li_fused_kernel(const float* __restrict__ X,
                     const float* __restrict__ W,
                     const float* __restrict__ bias,
                     float* __restrict__ out)
{
    __shared__ float As[BK][BM];   // A tile, transposed: As[k][m]
    __shared__ float Bs[BK][BN];   // B tile: Bs[k][n]

    const int tid = threadIdx.x;
    const int bm0 = blockIdx.y * BM;   // row base of this CTA
    const int bn0 = blockIdx.x * BN;   // col base of this CTA

    // micro-tile coords: 16 threads across N, 16 down M
    const int tx = tid & 15;           // 0..15
    const int ty = tid >> 4;           // 0..15
    const int tn0 = tx * TN;           // 0..120
    const int tm0 = ty * TM;           // 0..120

    float acc[TM][TN];
    #pragma unroll
    for (int i = 0; i < TM; ++i)
        #pragma unroll
        for (int j = 0; j < TN; ++j)
            acc[i][j] = 0.0f;

    for (int k0 = 0; k0 < NDIM; k0 += BK) {
        // ---- load A tile (BM x BK) as float4, store transposed ----
        #pragma unroll
        for (int t = 0; t < 2; ++t) {
            int idx = tid + t * NTHREADS;      // 0..511  (512 float4s)
            int row = idx >> 2;                // 0..127
            int c4  = idx & 3;                 // 0..3  (4 float4 per 16-wide row)
            const float4 v = *reinterpret_cast<const float4*>(
                &X[(size_t)(bm0 + row) * NDIM + k0 + c4 * 4]);
            As[c4 * 4 + 0][row] = v.x;
            As[c4 * 4 + 1][row] = v.y;
            As[c4 * 4 + 2][row] = v.z;
            As[c4 * 4 + 3][row] = v.w;
        }
        // ---- load B tile (BK x BN) as float4, zero the diagonal ----
        #pragma unroll
        for (int t = 0; t < 2; ++t) {
            int idx = tid + t * NTHREADS;      // 0..511
            int row = idx >> 5;                // 0..15 (k within tile)
            int c4  = idx & 31;                // 0..31 (float4 within 128-wide row)
            int gk = k0 + row;
            int gn = bn0 + c4 * 4;
            float4 v = *reinterpret_cast<const float4*>(&W[(size_t)gk * NDIM + gn]);
            if (gk == gn + 0) v.x = 0.0f;
            if (gk == gn + 1) v.y = 0.0f;
            if (gk == gn + 2) v.z = 0.0f;
            if (gk == gn + 3) v.w = 0.0f;
            *reinterpret_cast<float4*>(&Bs[row][c4 * 4]) = v;
        }
        __syncthreads();

        // ---- compute 8x8 per thread over BK ----
        #pragma unroll
        for (int kk = 0; kk < BK; ++kk) {
            float4 a0 = *reinterpret_cast<const float4*>(&As[kk][tm0]);
            float4 a1 = *reinterpret_cast<const float4*>(&As[kk][tm0 + 4]);
            float4 b0 = *reinterpret_cast<const float4*>(&Bs[kk][tn0]);
            float4 b1 = *reinterpret_cast<const float4*>(&Bs[kk][tn0 + 4]);
            float a[TM] = {a0.x, a0.y, a0.z, a0.w, a1.x, a1.y, a1.z, a1.w};
            float b[TN] = {b0.x, b0.y, b0.z, b0.w, b1.x, b1.y, b1.z, b1.w};
            #pragma unroll
            for (int i = 0; i < TM; ++i)
                #pragma unroll
                for (int j = 0; j < TN; ++j)
                    acc[i][j] = fmaf(a[i], b[j], acc[i][j]);
        }
        __syncthreads();
    }

    // ---- epilogue: gate = (acc + b) > 0; out = X * gate ----
    // preload bias for this thread's 8 columns
    float bv[TN];
    #pragma unroll
    for (int j = 0; j < TN; ++j)
        bv[j] = bias[bn0 + tn0 + j];

    #pragma unroll
    for (int i = 0; i < TM; ++i) {
        const int gm = bm0 + tm0 + i;
        #pragma unroll
        for (int jj = 0; jj < TN; jj += 4) {
            const int gn = bn0 + tn0 + jj;
            const float4 xv = *reinterpret_cast<const float4*>(
                &X[(size_t)gm * NDIM + gn]);
            float4 o;
            o.x = (acc[i][jj + 0] + bv[jj + 0]) > 0.0f ? xv.x : 0.0f;
            o.y = (acc[i][jj + 1] + bv[jj + 1]) > 0.0f ? xv.y : 0.0f;
            o.z = (acc[i][jj + 2] + bv[jj + 2]) > 0.0f ? xv.z : 0.0f;
            o.w = (acc[i][jj + 3] + bv[jj + 3]) > 0.0f ? xv.w : 0.0f;
            *reinterpret_cast<float4*>(&out[(size_t)gm * NDIM + gn]) = o;
        }
    }
}

extern "C" void kernel_launch(void* const* d_in, const int* in_sizes, int n_in,
                              void* d_out, int out_size)
{
    const float* X    = (const float*)d_in[0];   // (8,4096,512) fp32
    const float* W    = (const float*)d_in[1];   // (512,512) fp32
    const float* bias = (const float*)d_in[2];   // (512,) fp32
    float* out = (float*)d_out;

    const int M = in_sizes[0] / NDIM;            // 32768
    dim3 grid(NDIM / BN, M / BM);                // (4, 256)
    li_fused_kernel<<<grid, NTHREADS>>>(X, W, bias, out);
}

// round 2
// speedup vs baseline: 1.0011x; 1.0011x over previous
#include <cuda_runtime.h>

// LateralInhibition: out = X * ((X @ W_diag0 + b) > 0)
// X: (M=32768, 512) fp32 row-major, W: (512,512) fp32 row-major (K-major),
// b: (512,) fp32. Fused SIMT fp32 GEMM + gate epilogue.

#define NDIM 512
#define BM 128
#define BN 128
#define BK 16
#define TM 8
#define TN 8
#define NTHREADS 256

__global__ __launch_bounds__(NTHREADS, 2)
void li_fused_kernel(const float* __restrict__ X,
                     const float* __restrict__ W,
                     const float* __restrict__ bias,
                     float* __restrict__ out)
{
    __shared__ float As[BK][BM];   // A tile, transposed: As[k][m]
    __shared__ float Bs[BK][BN];   // B tile: Bs[k][n]

    const int tid = threadIdx.x;
    const int bm0 = blockIdx.y * BM;   // row base of this CTA
    const int bn0 = blockIdx.x * BN;   // col base of this CTA

    // micro-tile coords: 16 threads across N, 16 down M
    const int tx = tid & 15;           // 0..15
    const int ty = tid >> 4;           // 0..15
    const int tn0 = tx * TN;           // 0..120
    const int tm0 = ty * TM;           // 0..120

    float acc[TM][TN];
    #pragma unroll
    for (int i = 0; i < TM; ++i)
        #pragma unroll
        for (int j = 0; j < TN; ++j)
            acc[i][j] = 0.0f;

    for (int k0 = 0; k0 < NDIM; k0 += BK) {
        // ---- load A tile (BM x BK) as float4, store transposed ----
        #pragma unroll
        for (int t = 0; t < 2; ++t) {
            int idx = tid + t * NTHREADS;      // 0..511  (512 float4s)
            int row = idx >> 2;                // 0..127
            int c4  = idx & 3;                 // 0..3  (4 float4 per 16-wide row)
            const float4 v = *reinterpret_cast<const float4*>(
                &X[(size_t)(bm0 + row) * NDIM + k0 + c4 * 4]);
            As[c4 * 4 + 0][row] = v.x;
            As[c4 * 4 + 1][row] = v.y;
            As[c4 * 4 + 2][row] = v.z;
            As[c4 * 4 + 3][row] = v.w;
        }
        // ---- load B tile (BK x BN) as float4, zero the diagonal ----
        #pragma unroll
        for (int t = 0; t < 2; ++t) {
            int idx = tid + t * NTHREADS;      // 0..511
            int row = idx >> 5;                // 0..15 (k within tile)
            int c4  = idx & 31;                // 0..31 (float4 within 128-wide row)
            int gk = k0 + row;
            int gn = bn0 + c4 * 4;
            float4 v = *reinterpret_cast<const float4*>(&W[(size_t)gk * NDIM + gn]);
            if (gk == gn + 0) v.x = 0.0f;
            if (gk == gn + 1) v.y = 0.0f;
            if (gk == gn + 2) v.z = 0.0f;
            if (gk == gn + 3) v.w = 0.0f;
            *reinterpret_cast<float4*>(&Bs[row][c4 * 4]) = v;
        }
        __syncthreads();

        // ---- compute 8x8 per thread over BK ----
        #pragma unroll
        for (int kk = 0; kk < BK; ++kk) {
            float4 a0 = *reinterpret_cast<const float4*>(&As[kk][tm0]);
            float4 a1 = *reinterpret_cast<const float4*>(&As[kk][tm0 + 4]);
            float4 b0 = *reinterpret_cast<const float4*>(&Bs[kk][tn0]);
            float4 b1 = *reinterpret_cast<const float4*>(&Bs[kk][tn0 + 4]);
            float a[TM] = {a0.x, a0.y, a0.z, a0.w, a1.x, a1.y, a1.z, a1.w};
            float b[TN] = {b0.x, b0.y, b0.z, b0.w, b1.x, b1.y, b1.z, b1.w};
            #pragma unroll
            for (int i = 0; i < TM; ++i)
                #pragma unroll
                for (int j = 0; j < TN; ++j)
                    acc[i][j] = fmaf(a[i], b[j], acc[i][j]);
        }
        __syncthreads();
    }

    // ---- epilogue: gate = (acc + b) > 0; out = X * gate ----
    // preload bias for this thread's 8 columns
    float bv[TN];
    #pragma unroll
    for (int j = 0; j < TN; ++j)
        bv[j] = bias[bn0 + tn0 + j];

    #pragma unroll
    for (int i = 0; i < TM; ++i) {
        const int gm = bm0 + tm0 + i;
        #pragma unroll
        for (int jj = 0; jj < TN; jj += 4) {
            const int gn = bn0 + tn0 + jj;
            const float4 xv = *reinterpret_cast<const float4*>(
                &X[(size_t)gm * NDIM + gn]);
            float4 o;
            o.x = (acc[i][jj + 0] + bv[jj + 0]) > 0.0f ? xv.x : 0.0f;
            o.y = (acc[i][jj + 1] + bv[jj + 1]) > 0.0f ? xv.y : 0.0f;
            o.z = (acc[i][jj + 2] + bv[jj + 2]) > 0.0f ? xv.z : 0.0f;
            o.w = (acc[i][jj + 3] + bv[jj + 3]) > 0.0f ? xv.w : 0.0f;
            *reinterpret_cast<float4*>(&out[(size_t)gm * NDIM + gn]) = o;
        }
    }
}

extern "C" void kernel_launch(void* const* d_in, const int* in_sizes, int n_in,
                              void* d_out, int out_size)
{
    const float* X    = (const float*)d_in[0];   // (8,4096,512) fp32
    const float* W    = (const float*)d_in[1];   // (512,512) fp32
    const float* bias = (const float*)d_in[2];   // (512,) fp32
    float* out = (float*)d_out;

    const int M = in_sizes[0] / NDIM;            // 32768
    dim3 grid(NDIM / BN, M / BM);                // (4, 256)
    li_fused_kernel<<<grid, NTHREADS>>>(X, W, bias, out);
}